// round 15
// baseline (speedup 1.0000x reference)
#include <cuda_runtime.h>
#include <cuda_fp16.h>
#include <cstdint>

// Fused 3D windowed attention block — fp16 tensor-core, minimal splits.
// R15 = R14 + Q fused into the K/V GEMM pass (single A read for QKV) + Q 1-term.
// Terms: QKV weights hi-only; PV 1-term; conv 2-term (Y hi x W hi+lo).
// 1 window/CTA, 512 threads (16 warps = 2 wm x 8 wn), 2 CTAs/SM.

#define D0 30
#define H0 62
#define W0 126
#define MTOT (30*62*126)

#define AST 136     // halves/row, A & Y tiles (64 rows)
#define KST 136     // halves/row, K hi tile (64 rows)
#define VTST 72     // halves/row, Vt hi tile (128 dim rows x 64 keys + pad)

#define SM_AHI  0          // x hi, later Y hi   (17408 B)
#define SM_KHI  17408      // K hi               (17408 B)
#define SM_VTHI 34816      // Vt hi              (18432 B)
#define SM_BIAS 53248      // 384 f32            (1536 B)
#define SMEM_BYTES 54784

// weights in B-fragment order: [mat 0..3][wn 0..7][kk 0..7][lane 0..31] x uint4
// mats: 0=Q, 1=K, 2=V, 3=conv
__device__ __align__(256) uint4 g_bh4[4 * 8 * 8 * 32];
__device__ __align__(256) uint4 g_bl4[4 * 8 * 8 * 32];

__device__ __forceinline__ uint32_t smem_u32(const void* p) {
    uint32_t a;
    asm("{ .reg .u64 t; cvta.to.shared.u64 t, %1; cvt.u32.u64 %0, t; }"
        : "=r"(a) : "l"(p));
    return a;
}
__device__ __forceinline__ void ldsm4(uint32_t (&r)[4], uint32_t addr) {
    asm volatile("ldmatrix.sync.aligned.m8n8.x4.shared.b16 {%0,%1,%2,%3}, [%4];"
                 : "=r"(r[0]), "=r"(r[1]), "=r"(r[2]), "=r"(r[3]) : "r"(addr));
}
__device__ __forceinline__ void mma16816(float (&d)[4], const uint32_t (&a)[4],
                                         uint32_t b0, uint32_t b1) {
    asm volatile("mma.sync.aligned.m16n8k16.row.col.f32.f16.f16.f32 "
                 "{%0,%1,%2,%3}, {%4,%5,%6,%7}, {%8,%9}, {%0,%1,%2,%3};"
                 : "+f"(d[0]), "+f"(d[1]), "+f"(d[2]), "+f"(d[3])
                 : "r"(a[0]), "r"(a[1]), "r"(a[2]), "r"(a[3]), "r"(b0), "r"(b1));
}
__device__ __forceinline__ uint32_t h2u(__half a, __half b) {
    __half2 p = __halves2half2(a, b);
    return *(uint32_t*)&p;
}
__device__ __forceinline__ uint32_t packf16(float a, float b) {
    __half2 p = __floats2half2_rn(a, b);
    return *(uint32_t*)&p;
}
__device__ __forceinline__ uint32_t splitf16(float a, float b, uint32_t& lo) {
    __half h0 = __float2half_rn(a), h1 = __float2half_rn(b);
    __half l0 = __float2half_rn(a - __half2float(h0));
    __half l1 = __float2half_rn(b - __half2float(h1));
    lo = h2u(l0, l1);
    return h2u(h0, h1);
}

// ---------------- prep: weights -> fp16 hi/lo B-fragment layout ----------------
__global__ void prep_weights(const float* __restrict__ qkv_w,
                             const float* __restrict__ conv_w)
{
    int tid = blockIdx.x * 256 + threadIdx.x;    // 0..8191
    int lane = tid & 31;
    int kk   = (tid >> 5) & 7;
    int wn   = (tid >> 8) & 7;
    int mat  = tid >> 11;
    const float* W = (mat < 3) ? (qkv_w + mat * 16384) : conv_w;

    uint32_t hi[4], lo[4];
    #pragma unroll
    for (int r = 0; r < 4; ++r) {
        int n = wn * 16 + (r >> 1) * 8 + (lane >> 2);
        int k = kk * 16 + (r & 1) * 8 + 2 * (lane & 3);
        float v0 = W[n * 128 + k];
        float v1 = W[n * 128 + k + 1];
        hi[r] = splitf16(v0, v1, lo[r]);
    }
    g_bh4[tid] = make_uint4(hi[0], hi[1], hi[2], hi[3]);
    g_bl4[tid] = make_uint4(lo[0], lo[1], lo[2], lo[3]);
}

// ---------------- main kernel ----------------
__global__ void __launch_bounds__(512, 2)
fused_window_attn_mma(const float* __restrict__ x,
                      const float* __restrict__ qkv_b,
                      const float* __restrict__ conv_b,
                      float* __restrict__ out)
{
    extern __shared__ char smemc[];
    const uint32_t sb = smem_u32(smemc);
    float* biasS = (float*)(smemc + SM_BIAS);

    const int t    = threadIdx.x;
    const int wid  = t >> 5;
    const int lane = t & 31;
    const int wm = wid >> 3;
    const int wn = wid & 7;
    const int wi = blockIdx.x;
    const int bz = wi >> 9, by = (wi >> 5) & 15, bx = wi & 31;
    const int z0 = bz * 4, y0 = by * 4, x0 = bx * 4;

    // ---- phase 1: gather x -> A hi (fp16), bias ----
    #pragma unroll
    for (int it = 0; it < 8; ++it) {
        int idx = t + 512 * it;
        int l  = idx & 63;
        int cp = idx >> 6;
        int gz = z0 + (l >> 4);
        int gy = y0 + ((l >> 2) & 3);
        int gx = x0 + (l & 3);
        float v0 = 0.f, v1 = 0.f;
        if (gz < D0 && gy < H0 && gx < W0) {
            size_t base = (size_t)(gz * H0 + gy) * W0 + gx;
            v0 = x[(size_t)(2 * cp) * MTOT + base];
            v1 = x[(size_t)(2 * cp + 1) * MTOT + base];
        }
        *(uint32_t*)(smemc + SM_AHI + (l * AST + 2 * cp) * 2) = packf16(v0, v1);
    }
    if (t < 384) biasS[t] = qkv_b[t];
    __syncthreads();

    const uint32_t aHi = sb + SM_AHI;
    const int fragbase = wn * 8 * 32 + lane;
    const uint4* bh = g_bh4 + fragbase;              // +mat*2048 at use sites
    const uint4* blC = g_bl4 + 3 * 2048 + fragbase;

    const int r8 = lane & 7, g8 = lane >> 3;
    const uint32_t aoff = (uint32_t)(((wm * 32 + r8 + 8 * (g8 & 1)) * AST + 8 * (g8 >> 1)) * 2);

    const int erow = wm * 32 + (lane >> 2);
    const int ecol = wn * 16 + 2 * (lane & 3);

    uint32_t qh[2][4];
    // ---- fused Q+K+V GEMMs (one A pass, 1-term W-hi each) ----
    {
        float accQ[2][2][4] = {};
        float accK[2][2][4] = {};
        float accV[2][2][4] = {};
        #pragma unroll
        for (int kk = 0; kk < 8; ++kk) {
            uint32_t ah[2][4];
            #pragma unroll
            for (int mt = 0; mt < 2; ++mt)
                ldsm4(ah[mt], aHi + aoff + (uint32_t)((mt * 16 * AST + kk * 16) * 2));
            {
                uint4 B = __ldg(bh + 0 * 2048 + kk * 32);
                #pragma unroll
                for (int mt = 0; mt < 2; ++mt) {
                    mma16816(accQ[mt][0], ah[mt], B.x, B.y);
                    mma16816(accQ[mt][1], ah[mt], B.z, B.w);
                }
            }
            {
                uint4 B = __ldg(bh + 1 * 2048 + kk * 32);
                #pragma unroll
                for (int mt = 0; mt < 2; ++mt) {
                    mma16816(accK[mt][0], ah[mt], B.x, B.y);
                    mma16816(accK[mt][1], ah[mt], B.z, B.w);
                }
            }
            {
                uint4 B = __ldg(bh + 2 * 2048 + kk * 32);
                #pragma unroll
                for (int mt = 0; mt < 2; ++mt) {
                    mma16816(accV[mt][0], ah[mt], B.x, B.y);
                    mma16816(accV[mt][1], ah[mt], B.z, B.w);
                }
            }
        }
        // Q epilogue -> register fp16 fragments
        #pragma unroll
        for (int mt = 0; mt < 2; ++mt)
            #pragma unroll
            for (int nt = 0; nt < 2; ++nt) {
                int col = ecol + nt * 8;
                float2 bv = *(const float2*)(biasS + col);
                qh[mt][2 * nt]     = packf16(accQ[mt][nt][0] + bv.x, accQ[mt][nt][1] + bv.y);
                qh[mt][2 * nt + 1] = packf16(accQ[mt][nt][2] + bv.x, accQ[mt][nt][3] + bv.y);
            }
        // K epilogue -> K hi smem
        #pragma unroll
        for (int mt = 0; mt < 2; ++mt)
            #pragma unroll
            for (int nt = 0; nt < 2; ++nt) {
                int col = ecol + nt * 8;
                float2 bv = *(const float2*)(biasS + 128 + col);
                int r0 = erow + mt * 16;
                *(uint32_t*)(smemc + SM_KHI + (r0 * KST + col) * 2) =
                    packf16(accK[mt][nt][0] + bv.x, accK[mt][nt][1] + bv.y);
                *(uint32_t*)(smemc + SM_KHI + ((r0 + 8) * KST + col) * 2) =
                    packf16(accK[mt][nt][2] + bv.x, accK[mt][nt][3] + bv.y);
            }
        // V epilogue -> Vt hi smem (transposed)
        #pragma unroll
        for (int mt = 0; mt < 2; ++mt)
            #pragma unroll
            for (int nt = 0; nt < 2; ++nt) {
                int col = ecol + nt * 8;
                float2 bv = *(const float2*)(biasS + 256 + col);
                int key = erow + mt * 16;
                int base0 = (col)     * VTST;
                int base1 = (col + 1) * VTST;
                *(__half*)(smemc + SM_VTHI + 2 * (base0 + key))     = __float2half_rn(accV[mt][nt][0] + bv.x);
                *(__half*)(smemc + SM_VTHI + 2 * (base1 + key))     = __float2half_rn(accV[mt][nt][1] + bv.y);
                *(__half*)(smemc + SM_VTHI + 2 * (base0 + key + 8)) = __float2half_rn(accV[mt][nt][2] + bv.x);
                *(__half*)(smemc + SM_VTHI + 2 * (base1 + key + 8)) = __float2half_rn(accV[mt][nt][3] + bv.y);
            }
    }
    __syncthreads();   // K/Vt visible; all A reads done

    // ---- attention, warp = (rowhalf wm, head wn) ----
    unsigned long long pm = 0ull;
    if (bz == 7)  pm |= 0xFFFFFFFF00000000ull;
    if (by == 15) pm |= 0xFF00FF00FF00FF00ull;
    if (bx == 31) pm |= 0xCCCCCCCCCCCCCCCCull;

    const int head = wn;
    unsigned rp[2][2];
    #pragma unroll
    for (int mt = 0; mt < 2; ++mt) {
        int r0 = wm * 32 + mt * 16 + (lane >> 2);
        rp[mt][0] = (unsigned)(pm >> r0) & 1u;
        rp[mt][1] = (unsigned)(pm >> (r0 + 8)) & 1u;
    }

    const uint32_t koff = (uint32_t)(((r8 + 8 * ((lane >> 4) & 1)) * KST
                                      + head * 16 + 8 * ((lane >> 3) & 1)) * 2);
    const uint32_t voff = (uint32_t)(((head * 16 + r8 + 8 * ((lane >> 4) & 1)) * VTST
                                      + 8 * ((lane >> 3) & 1)) * 2);

    float oacc[2][2][4] = {};
    float rsum[2][2] = {};

    #pragma unroll
    for (int g4 = 0; g4 < 4; ++g4) {
        uint32_t kh[4];
        ldsm4(kh, sb + SM_KHI + koff + (uint32_t)(g4 * 16 * KST * 2));

        float sacc[2][2][4] = {};
        #pragma unroll
        for (int mt = 0; mt < 2; ++mt)
            #pragma unroll
            for (int s = 0; s < 2; ++s)
                mma16816(sacc[mt][s], qh[mt], kh[2 * s], kh[2 * s + 1]);

        uint32_t ph[2][4];
        #pragma unroll
        for (int s = 0; s < 2; ++s) {
            int k0 = g4 * 16 + s * 8 + 2 * (lane & 3);
            unsigned cp0 = (unsigned)(pm >> k0) & 1u;
            unsigned cp1 = (unsigned)(pm >> (k0 + 1)) & 1u;
            #pragma unroll
            for (int mt = 0; mt < 2; ++mt) {
                float e0 = (cp0 == rp[mt][0]) ? __expf(0.25f * sacc[mt][s][0]) : 0.f;
                float e1 = (cp1 == rp[mt][0]) ? __expf(0.25f * sacc[mt][s][1]) : 0.f;
                float e2 = (cp0 == rp[mt][1]) ? __expf(0.25f * sacc[mt][s][2]) : 0.f;
                float e3 = (cp1 == rp[mt][1]) ? __expf(0.25f * sacc[mt][s][3]) : 0.f;
                rsum[mt][0] += e0 + e1;
                rsum[mt][1] += e2 + e3;
                ph[mt][2 * s]     = packf16(e0, e1);
                ph[mt][2 * s + 1] = packf16(e2, e3);
            }
        }

        uint32_t vh[4];
        ldsm4(vh, sb + SM_VTHI + voff + (uint32_t)(g4 * 16 * 2));
        #pragma unroll
        for (int mt = 0; mt < 2; ++mt)
            #pragma unroll
            for (int sp = 0; sp < 2; ++sp)
                mma16816(oacc[mt][sp], ph[mt], vh[2 * sp], vh[2 * sp + 1]);
    }

    // quad-reduce row sums, normalize, store Y hi into A region (x is dead)
    #pragma unroll
    for (int mt = 0; mt < 2; ++mt)
        #pragma unroll
        for (int h = 0; h < 2; ++h) {
            rsum[mt][h] += __shfl_xor_sync(0xFFFFFFFFu, rsum[mt][h], 1);
            rsum[mt][h] += __shfl_xor_sync(0xFFFFFFFFu, rsum[mt][h], 2);
            rsum[mt][h] = 1.0f / rsum[mt][h];
        }
    #pragma unroll
    for (int mt = 0; mt < 2; ++mt)
        #pragma unroll
        for (int sp = 0; sp < 2; ++sp) {
            int col = head * 16 + sp * 8 + 2 * (lane & 3);
            int r0 = wm * 32 + mt * 16 + (lane >> 2);
            *(uint32_t*)(smemc + SM_AHI + (r0 * AST + col) * 2) =
                packf16(oacc[mt][sp][0] * rsum[mt][0], oacc[mt][sp][1] * rsum[mt][0]);
            *(uint32_t*)(smemc + SM_AHI + ((r0 + 8) * AST + col) * 2) =
                packf16(oacc[mt][sp][2] * rsum[mt][1], oacc[mt][sp][3] * rsum[mt][1]);
        }
    __syncthreads();   // Y tiles ready

    // ---- conv GEMM (2-term: Y hi x W hi/lo) + scattered output ----
    {
        float acc[2][2][4] = {};
        #pragma unroll
        for (int kk = 0; kk < 8; ++kk) {
            uint4 BH = __ldg(bh + 3 * 2048 + kk * 32);
            uint4 BL = __ldg(blC + kk * 32);
            uint32_t ah[2][4];
            #pragma unroll
            for (int mt = 0; mt < 2; ++mt)
                ldsm4(ah[mt], aHi + aoff + (uint32_t)((mt * 16 * AST + kk * 16) * 2));
            #pragma unroll
            for (int mt = 0; mt < 2; ++mt) {
                mma16816(acc[mt][0], ah[mt], BH.x, BH.y);
                mma16816(acc[mt][0], ah[mt], BL.x, BL.y);
                mma16816(acc[mt][1], ah[mt], BH.z, BH.w);
                mma16816(acc[mt][1], ah[mt], BL.z, BL.w);
            }
        }
        #pragma unroll
        for (int mt = 0; mt < 2; ++mt) {
            int m0 = erow + mt * 16;
            int m1 = m0 + 8;
            int gz0 = z0 + (m0 >> 4), gy0 = y0 + ((m0 >> 2) & 3), gx0 = x0 + (m0 & 3);
            int gz1 = z0 + (m1 >> 4), gy1 = y0 + ((m1 >> 2) & 3), gx1 = x0 + (m1 & 3);
            bool ok0 = (gz0 < D0 && gy0 < H0 && gx0 < W0);
            bool ok1 = (gz1 < D0 && gy1 < H0 && gx1 < W0);
            size_t va0 = (size_t)(gz0 * H0 + gy0) * W0 + gx0;
            size_t va1 = (size_t)(gz1 * H0 + gy1) * W0 + gx1;
            #pragma unroll
            for (int nt = 0; nt < 2; ++nt) {
                int o = ecol + nt * 8;
                float2 cb = *(const float2*)(conv_b + o);
                if (ok0) {
                    out[(size_t)o * MTOT + va0]       = acc[mt][nt][0] + cb.x;
                    out[(size_t)(o + 1) * MTOT + va0] = acc[mt][nt][1] + cb.y;
                }
                if (ok1) {
                    out[(size_t)o * MTOT + va1]       = acc[mt][nt][2] + cb.x;
                    out[(size_t)(o + 1) * MTOT + va1] = acc[mt][nt][3] + cb.y;
                }
            }
        }
    }
}

extern "C" void kernel_launch(void* const* d_in, const int* in_sizes, int n_in,
                              void* d_out, int out_size)
{
    const float* x      = (const float*)d_in[0];
    const float* qkv_b  = (const float*)d_in[2];
    const float* conv_b = (const float*)d_in[4];
    float* out = (float*)d_out;

    prep_weights<<<32, 256>>>((const float*)d_in[1], (const float*)d_in[3]);

    cudaFuncSetAttribute(fused_window_attn_mma,
                         cudaFuncAttributeMaxDynamicSharedMemorySize, SMEM_BYTES);

    fused_window_attn_mma<<<4096, 512, SMEM_BYTES>>>(x, qkv_b, conv_b, out);
}

// round 16
// speedup vs baseline: 1.3131x; 1.3131x over previous
#include <cuda_runtime.h>
#include <cuda_fp16.h>
#include <cstdint>

// Fused 3D windowed attention block — fp16 tensor-core, 1-term weights everywhere.
// R16 = R14 structure (fused K/V pass + separate Q pass + conv pass; registers safe)
//       with W-lo terms dropped for Q and conv (empirically costless: R15 showed
//       Q 1-term moved rel_err by 7e-8).
// 1 window/CTA, 512 threads (16 warps = 2 wm x 8 wn), 2 CTAs/SM.

#define D0 30
#define H0 62
#define W0 126
#define MTOT (30*62*126)

#define AST 136     // halves/row, A & Y tiles (64 rows)
#define KST 136     // halves/row, K hi tile (64 rows)
#define VTST 72     // halves/row, Vt hi tile (128 dim rows x 64 keys + pad)

#define SM_AHI  0          // x hi, later Y hi   (17408 B)
#define SM_KHI  17408      // K hi               (17408 B)
#define SM_VTHI 34816      // Vt hi              (18432 B)
#define SM_BIAS 53248      // 384 f32            (1536 B)
#define SMEM_BYTES 54784

// weights in B-fragment order: [mat 0..3][wn 0..7][kk 0..7][lane 0..31] x uint4
// mats: 0=Q, 1=K, 2=V, 3=conv  (hi only is used by the kernel now)
__device__ __align__(256) uint4 g_bh4[4 * 8 * 8 * 32];

__device__ __forceinline__ uint32_t smem_u32(const void* p) {
    uint32_t a;
    asm("{ .reg .u64 t; cvta.to.shared.u64 t, %1; cvt.u32.u64 %0, t; }"
        : "=r"(a) : "l"(p));
    return a;
}
__device__ __forceinline__ void ldsm4(uint32_t (&r)[4], uint32_t addr) {
    asm volatile("ldmatrix.sync.aligned.m8n8.x4.shared.b16 {%0,%1,%2,%3}, [%4];"
                 : "=r"(r[0]), "=r"(r[1]), "=r"(r[2]), "=r"(r[3]) : "r"(addr));
}
__device__ __forceinline__ void mma16816(float (&d)[4], const uint32_t (&a)[4],
                                         uint32_t b0, uint32_t b1) {
    asm volatile("mma.sync.aligned.m16n8k16.row.col.f32.f16.f16.f32 "
                 "{%0,%1,%2,%3}, {%4,%5,%6,%7}, {%8,%9}, {%0,%1,%2,%3};"
                 : "+f"(d[0]), "+f"(d[1]), "+f"(d[2]), "+f"(d[3])
                 : "r"(a[0]), "r"(a[1]), "r"(a[2]), "r"(a[3]), "r"(b0), "r"(b1));
}
__device__ __forceinline__ uint32_t packf16(float a, float b) {
    __half2 p = __floats2half2_rn(a, b);
    return *(uint32_t*)&p;
}

// ---------------- prep: weights -> fp16 hi B-fragment layout ----------------
__global__ void prep_weights(const float* __restrict__ qkv_w,
                             const float* __restrict__ conv_w)
{
    int tid = blockIdx.x * 256 + threadIdx.x;    // 0..8191
    int lane = tid & 31;
    int kk   = (tid >> 5) & 7;
    int wn   = (tid >> 8) & 7;
    int mat  = tid >> 11;
    const float* W = (mat < 3) ? (qkv_w + mat * 16384) : conv_w;

    uint32_t hi[4];
    #pragma unroll
    for (int r = 0; r < 4; ++r) {
        int n = wn * 16 + (r >> 1) * 8 + (lane >> 2);
        int k = kk * 16 + (r & 1) * 8 + 2 * (lane & 3);
        hi[r] = packf16(W[n * 128 + k], W[n * 128 + k + 1]);
    }
    g_bh4[tid] = make_uint4(hi[0], hi[1], hi[2], hi[3]);
}

// ---------------- main kernel ----------------
__global__ void __launch_bounds__(512, 2)
fused_window_attn_mma(const float* __restrict__ x,
                      const float* __restrict__ qkv_b,
                      const float* __restrict__ conv_b,
                      float* __restrict__ out)
{
    extern __shared__ char smemc[];
    const uint32_t sb = smem_u32(smemc);
    float* biasS = (float*)(smemc + SM_BIAS);

    const int t    = threadIdx.x;
    const int wid  = t >> 5;
    const int lane = t & 31;
    const int wm = wid >> 3;
    const int wn = wid & 7;
    const int wi = blockIdx.x;
    const int bz = wi >> 9, by = (wi >> 5) & 15, bx = wi & 31;
    const int z0 = bz * 4, y0 = by * 4, x0 = bx * 4;

    // ---- phase 1: gather x -> A hi (fp16), bias ----
    #pragma unroll
    for (int it = 0; it < 8; ++it) {
        int idx = t + 512 * it;
        int l  = idx & 63;
        int cp = idx >> 6;
        int gz = z0 + (l >> 4);
        int gy = y0 + ((l >> 2) & 3);
        int gx = x0 + (l & 3);
        float v0 = 0.f, v1 = 0.f;
        if (gz < D0 && gy < H0 && gx < W0) {
            size_t base = (size_t)(gz * H0 + gy) * W0 + gx;
            v0 = x[(size_t)(2 * cp) * MTOT + base];
            v1 = x[(size_t)(2 * cp + 1) * MTOT + base];
        }
        *(uint32_t*)(smemc + SM_AHI + (l * AST + 2 * cp) * 2) = packf16(v0, v1);
    }
    if (t < 384) biasS[t] = qkv_b[t];
    __syncthreads();

    const uint32_t aHi = sb + SM_AHI;
    const int fragbase = wn * 8 * 32 + lane;
    const uint4* bhQ = g_bh4 + 0 * 2048 + fragbase;
    const uint4* bhK = g_bh4 + 1 * 2048 + fragbase;
    const uint4* bhV = g_bh4 + 2 * 2048 + fragbase;
    const uint4* bhC = g_bh4 + 3 * 2048 + fragbase;

    const int r8 = lane & 7, g8 = lane >> 3;
    const uint32_t aoff = (uint32_t)(((wm * 32 + r8 + 8 * (g8 & 1)) * AST + 8 * (g8 >> 1)) * 2);

    const int erow = wm * 32 + (lane >> 2);
    const int ecol = wn * 16 + 2 * (lane & 3);

    // ---- fused K+V GEMMs (one A pass, 1-term W-hi) ----
    {
        float accK[2][2][4] = {};
        float accV[2][2][4] = {};
        #pragma unroll
        for (int kk = 0; kk < 8; ++kk) {
            uint32_t ah[2][4];
            #pragma unroll
            for (int mt = 0; mt < 2; ++mt)
                ldsm4(ah[mt], aHi + aoff + (uint32_t)((mt * 16 * AST + kk * 16) * 2));
            uint4 BK = __ldg(bhK + kk * 32);
            uint4 BV = __ldg(bhV + kk * 32);
            #pragma unroll
            for (int mt = 0; mt < 2; ++mt) {
                mma16816(accK[mt][0], ah[mt], BK.x, BK.y);
                mma16816(accK[mt][1], ah[mt], BK.z, BK.w);
                mma16816(accV[mt][0], ah[mt], BV.x, BV.y);
                mma16816(accV[mt][1], ah[mt], BV.z, BV.w);
            }
        }
        // K epilogue -> K hi smem
        #pragma unroll
        for (int mt = 0; mt < 2; ++mt)
            #pragma unroll
            for (int nt = 0; nt < 2; ++nt) {
                int col = ecol + nt * 8;
                float2 bv = *(const float2*)(biasS + 128 + col);
                int r0 = erow + mt * 16;
                *(uint32_t*)(smemc + SM_KHI + (r0 * KST + col) * 2) =
                    packf16(accK[mt][nt][0] + bv.x, accK[mt][nt][1] + bv.y);
                *(uint32_t*)(smemc + SM_KHI + ((r0 + 8) * KST + col) * 2) =
                    packf16(accK[mt][nt][2] + bv.x, accK[mt][nt][3] + bv.y);
            }
        // V epilogue -> Vt hi smem (transposed)
        #pragma unroll
        for (int mt = 0; mt < 2; ++mt)
            #pragma unroll
            for (int nt = 0; nt < 2; ++nt) {
                int col = ecol + nt * 8;
                float2 bv = *(const float2*)(biasS + 256 + col);
                int key = erow + mt * 16;
                int base0 = (col)     * VTST;
                int base1 = (col + 1) * VTST;
                *(__half*)(smemc + SM_VTHI + 2 * (base0 + key))     = __float2half_rn(accV[mt][nt][0] + bv.x);
                *(__half*)(smemc + SM_VTHI + 2 * (base1 + key))     = __float2half_rn(accV[mt][nt][1] + bv.y);
                *(__half*)(smemc + SM_VTHI + 2 * (base0 + key + 8)) = __float2half_rn(accV[mt][nt][2] + bv.x);
                *(__half*)(smemc + SM_VTHI + 2 * (base1 + key + 8)) = __float2half_rn(accV[mt][nt][3] + bv.y);
            }
    }

    // ---- Q GEMM (1-term; hi fragments stay in registers) ----
    uint32_t qh[2][4];
    {
        float acc[2][2][4] = {};
        #pragma unroll
        for (int kk = 0; kk < 8; ++kk) {
            uint4 BH = __ldg(bhQ + kk * 32);
            uint32_t ah[2][4];
            #pragma unroll
            for (int mt = 0; mt < 2; ++mt)
                ldsm4(ah[mt], aHi + aoff + (uint32_t)((mt * 16 * AST + kk * 16) * 2));
            #pragma unroll
            for (int mt = 0; mt < 2; ++mt) {
                mma16816(acc[mt][0], ah[mt], BH.x, BH.y);
                mma16816(acc[mt][1], ah[mt], BH.z, BH.w);
            }
        }
        #pragma unroll
        for (int mt = 0; mt < 2; ++mt)
            #pragma unroll
            for (int nt = 0; nt < 2; ++nt) {
                int col = ecol + nt * 8;
                float2 bv = *(const float2*)(biasS + col);
                qh[mt][2 * nt]     = packf16(acc[mt][nt][0] + bv.x, acc[mt][nt][1] + bv.y);
                qh[mt][2 * nt + 1] = packf16(acc[mt][nt][2] + bv.x, acc[mt][nt][3] + bv.y);
            }
    }
    __syncthreads();   // K/Vt visible; all A reads done

    // ---- attention, warp = (rowhalf wm, head wn) ----
    unsigned long long pm = 0ull;
    if (bz == 7)  pm |= 0xFFFFFFFF00000000ull;
    if (by == 15) pm |= 0xFF00FF00FF00FF00ull;
    if (bx == 31) pm |= 0xCCCCCCCCCCCCCCCCull;

    const int head = wn;
    unsigned rp[2][2];
    #pragma unroll
    for (int mt = 0; mt < 2; ++mt) {
        int r0 = wm * 32 + mt * 16 + (lane >> 2);
        rp[mt][0] = (unsigned)(pm >> r0) & 1u;
        rp[mt][1] = (unsigned)(pm >> (r0 + 8)) & 1u;
    }

    const uint32_t koff = (uint32_t)(((r8 + 8 * ((lane >> 4) & 1)) * KST
                                      + head * 16 + 8 * ((lane >> 3) & 1)) * 2);
    const uint32_t voff = (uint32_t)(((head * 16 + r8 + 8 * ((lane >> 4) & 1)) * VTST
                                      + 8 * ((lane >> 3) & 1)) * 2);

    float oacc[2][2][4] = {};
    float rsum[2][2] = {};

    #pragma unroll
    for (int g4 = 0; g4 < 4; ++g4) {
        uint32_t kh[4];
        ldsm4(kh, sb + SM_KHI + koff + (uint32_t)(g4 * 16 * KST * 2));

        float sacc[2][2][4] = {};
        #pragma unroll
        for (int mt = 0; mt < 2; ++mt)
            #pragma unroll
            for (int s = 0; s < 2; ++s)
                mma16816(sacc[mt][s], qh[mt], kh[2 * s], kh[2 * s + 1]);

        uint32_t ph[2][4];
        #pragma unroll
        for (int s = 0; s < 2; ++s) {
            int k0 = g4 * 16 + s * 8 + 2 * (lane & 3);
            unsigned cp0 = (unsigned)(pm >> k0) & 1u;
            unsigned cp1 = (unsigned)(pm >> (k0 + 1)) & 1u;
            #pragma unroll
            for (int mt = 0; mt < 2; ++mt) {
                float e0 = (cp0 == rp[mt][0]) ? __expf(0.25f * sacc[mt][s][0]) : 0.f;
                float e1 = (cp1 == rp[mt][0]) ? __expf(0.25f * sacc[mt][s][1]) : 0.f;
                float e2 = (cp0 == rp[mt][1]) ? __expf(0.25f * sacc[mt][s][2]) : 0.f;
                float e3 = (cp1 == rp[mt][1]) ? __expf(0.25f * sacc[mt][s][3]) : 0.f;
                rsum[mt][0] += e0 + e1;
                rsum[mt][1] += e2 + e3;
                ph[mt][2 * s]     = packf16(e0, e1);
                ph[mt][2 * s + 1] = packf16(e2, e3);
            }
        }

        uint32_t vh[4];
        ldsm4(vh, sb + SM_VTHI + voff + (uint32_t)(g4 * 16 * 2));
        #pragma unroll
        for (int mt = 0; mt < 2; ++mt)
            #pragma unroll
            for (int sp = 0; sp < 2; ++sp)
                mma16816(oacc[mt][sp], ph[mt], vh[2 * sp], vh[2 * sp + 1]);
    }

    // quad-reduce row sums, normalize, store Y hi into A region (x is dead)
    #pragma unroll
    for (int mt = 0; mt < 2; ++mt)
        #pragma unroll
        for (int h = 0; h < 2; ++h) {
            rsum[mt][h] += __shfl_xor_sync(0xFFFFFFFFu, rsum[mt][h], 1);
            rsum[mt][h] += __shfl_xor_sync(0xFFFFFFFFu, rsum[mt][h], 2);
            rsum[mt][h] = 1.0f / rsum[mt][h];
        }
    #pragma unroll
    for (int mt = 0; mt < 2; ++mt)
        #pragma unroll
        for (int sp = 0; sp < 2; ++sp) {
            int col = head * 16 + sp * 8 + 2 * (lane & 3);
            int r0 = wm * 32 + mt * 16 + (lane >> 2);
            *(uint32_t*)(smemc + SM_AHI + (r0 * AST + col) * 2) =
                packf16(oacc[mt][sp][0] * rsum[mt][0], oacc[mt][sp][1] * rsum[mt][0]);
            *(uint32_t*)(smemc + SM_AHI + ((r0 + 8) * AST + col) * 2) =
                packf16(oacc[mt][sp][2] * rsum[mt][1], oacc[mt][sp][3] * rsum[mt][1]);
        }
    __syncthreads();   // Y tiles ready

    // ---- conv GEMM (1-term: Y hi x W hi) + scattered output ----
    {
        float acc[2][2][4] = {};
        #pragma unroll
        for (int kk = 0; kk < 8; ++kk) {
            uint4 BH = __ldg(bhC + kk * 32);
            uint32_t ah[2][4];
            #pragma unroll
            for (int mt = 0; mt < 2; ++mt)
                ldsm4(ah[mt], aHi + aoff + (uint32_t)((mt * 16 * AST + kk * 16) * 2));
            #pragma unroll
            for (int mt = 0; mt < 2; ++mt) {
                mma16816(acc[mt][0], ah[mt], BH.x, BH.y);
                mma16816(acc[mt][1], ah[mt], BH.z, BH.w);
            }
        }
        #pragma unroll
        for (int mt = 0; mt < 2; ++mt) {
            int m0 = erow + mt * 16;
            int m1 = m0 + 8;
            int gz0 = z0 + (m0 >> 4), gy0 = y0 + ((m0 >> 2) & 3), gx0 = x0 + (m0 & 3);
            int gz1 = z0 + (m1 >> 4), gy1 = y0 + ((m1 >> 2) & 3), gx1 = x0 + (m1 & 3);
            bool ok0 = (gz0 < D0 && gy0 < H0 && gx0 < W0);
            bool ok1 = (gz1 < D0 && gy1 < H0 && gx1 < W0);
            size_t va0 = (size_t)(gz0 * H0 + gy0) * W0 + gx0;
            size_t va1 = (size_t)(gz1 * H0 + gy1) * W0 + gx1;
            #pragma unroll
            for (int nt = 0; nt < 2; ++nt) {
                int o = ecol + nt * 8;
                float2 cb = *(const float2*)(conv_b + o);
                if (ok0) {
                    out[(size_t)o * MTOT + va0]       = acc[mt][nt][0] + cb.x;
                    out[(size_t)(o + 1) * MTOT + va0] = acc[mt][nt][1] + cb.y;
                }
                if (ok1) {
                    out[(size_t)o * MTOT + va1]       = acc[mt][nt][2] + cb.x;
                    out[(size_t)(o + 1) * MTOT + va1] = acc[mt][nt][3] + cb.y;
                }
            }
        }
    }
}

extern "C" void kernel_launch(void* const* d_in, const int* in_sizes, int n_in,
                              void* d_out, int out_size)
{
    const float* x      = (const float*)d_in[0];
    const float* qkv_b  = (const float*)d_in[2];
    const float* conv_b = (const float*)d_in[4];
    float* out = (float*)d_out;

    prep_weights<<<32, 256>>>((const float*)d_in[1], (const float*)d_in[3]);

    cudaFuncSetAttribute(fused_window_attn_mma,
                         cudaFuncAttributeMaxDynamicSharedMemorySize, SMEM_BYTES);

    fused_window_attn_mma<<<4096, 512, SMEM_BYTES>>>(x, qkv_b, conv_b, out);
}

// round 17
// speedup vs baseline: 1.4168x; 1.0790x over previous
#include <cuda_runtime.h>
#include <cuda_fp16.h>
#include <cstdint>

// Fused 3D windowed attention block — fp16 tensor-core, 1-term weights.
// R17 = R16 + CTA-uniform fast path for interior windows (pm==0: no mask ALU).
// 1 window/CTA, 512 threads (16 warps = 2 wm x 8 wn), 2 CTAs/SM.

#define D0 30
#define H0 62
#define W0 126
#define MTOT (30*62*126)

#define AST 136     // halves/row, A & Y tiles (64 rows)
#define KST 136     // halves/row, K hi tile (64 rows)
#define VTST 72     // halves/row, Vt hi tile (128 dim rows x 64 keys + pad)

#define SM_AHI  0          // x hi, later Y hi   (17408 B)
#define SM_KHI  17408      // K hi               (17408 B)
#define SM_VTHI 34816      // Vt hi              (18432 B)
#define SM_BIAS 53248      // 384 f32            (1536 B)
#define SMEM_BYTES 54784

// weights in B-fragment order: [mat 0..3][wn 0..7][kk 0..7][lane 0..31] x uint4
// mats: 0=Q, 1=K, 2=V, 3=conv  (hi parts only)
__device__ __align__(256) uint4 g_bh4[4 * 8 * 8 * 32];

__device__ __forceinline__ uint32_t smem_u32(const void* p) {
    uint32_t a;
    asm("{ .reg .u64 t; cvta.to.shared.u64 t, %1; cvt.u32.u64 %0, t; }"
        : "=r"(a) : "l"(p));
    return a;
}
__device__ __forceinline__ void ldsm4(uint32_t (&r)[4], uint32_t addr) {
    asm volatile("ldmatrix.sync.aligned.m8n8.x4.shared.b16 {%0,%1,%2,%3}, [%4];"
                 : "=r"(r[0]), "=r"(r[1]), "=r"(r[2]), "=r"(r[3]) : "r"(addr));
}
__device__ __forceinline__ void mma16816(float (&d)[4], const uint32_t (&a)[4],
                                         uint32_t b0, uint32_t b1) {
    asm volatile("mma.sync.aligned.m16n8k16.row.col.f32.f16.f16.f32 "
                 "{%0,%1,%2,%3}, {%4,%5,%6,%7}, {%8,%9}, {%0,%1,%2,%3};"
                 : "+f"(d[0]), "+f"(d[1]), "+f"(d[2]), "+f"(d[3])
                 : "r"(a[0]), "r"(a[1]), "r"(a[2]), "r"(a[3]), "r"(b0), "r"(b1));
}
__device__ __forceinline__ uint32_t packf16(float a, float b) {
    __half2 p = __floats2half2_rn(a, b);
    return *(uint32_t*)&p;
}

// ---------------- prep: weights -> fp16 hi B-fragment layout ----------------
__global__ void prep_weights(const float* __restrict__ qkv_w,
                             const float* __restrict__ conv_w)
{
    int tid = blockIdx.x * 256 + threadIdx.x;    // 0..8191
    int lane = tid & 31;
    int kk   = (tid >> 5) & 7;
    int wn   = (tid >> 8) & 7;
    int mat  = tid >> 11;
    const float* W = (mat < 3) ? (qkv_w + mat * 16384) : conv_w;

    uint32_t hi[4];
    #pragma unroll
    for (int r = 0; r < 4; ++r) {
        int n = wn * 16 + (r >> 1) * 8 + (lane >> 2);
        int k = kk * 16 + (r & 1) * 8 + 2 * (lane & 3);
        hi[r] = packf16(W[n * 128 + k], W[n * 128 + k + 1]);
    }
    g_bh4[tid] = make_uint4(hi[0], hi[1], hi[2], hi[3]);
}

// attention inner loop, templated on whether the pad mask is active
template<bool MASKED>
__device__ __forceinline__ void attn_loop(uint32_t sb,
                                          const uint32_t (&qh)[2][4],
                                          unsigned long long pm,
                                          int wm, int lane,
                                          uint32_t koff, uint32_t voff,
                                          float (&oacc)[2][2][4],
                                          float (&rsum)[2][2])
{
    unsigned rp[2][2];
    if (MASKED) {
        #pragma unroll
        for (int mt = 0; mt < 2; ++mt) {
            int r0 = wm * 32 + mt * 16 + (lane >> 2);
            rp[mt][0] = (unsigned)(pm >> r0) & 1u;
            rp[mt][1] = (unsigned)(pm >> (r0 + 8)) & 1u;
        }
    }

    #pragma unroll
    for (int g4 = 0; g4 < 4; ++g4) {
        uint32_t kh[4];
        ldsm4(kh, sb + SM_KHI + koff + (uint32_t)(g4 * 16 * KST * 2));

        float sacc[2][2][4] = {};
        #pragma unroll
        for (int mt = 0; mt < 2; ++mt)
            #pragma unroll
            for (int s = 0; s < 2; ++s)
                mma16816(sacc[mt][s], qh[mt], kh[2 * s], kh[2 * s + 1]);

        uint32_t ph[2][4];
        #pragma unroll
        for (int s = 0; s < 2; ++s) {
            if (MASKED) {
                int k0 = g4 * 16 + s * 8 + 2 * (lane & 3);
                unsigned cp0 = (unsigned)(pm >> k0) & 1u;
                unsigned cp1 = (unsigned)(pm >> (k0 + 1)) & 1u;
                #pragma unroll
                for (int mt = 0; mt < 2; ++mt) {
                    float e0 = (cp0 == rp[mt][0]) ? __expf(0.25f * sacc[mt][s][0]) : 0.f;
                    float e1 = (cp1 == rp[mt][0]) ? __expf(0.25f * sacc[mt][s][1]) : 0.f;
                    float e2 = (cp0 == rp[mt][1]) ? __expf(0.25f * sacc[mt][s][2]) : 0.f;
                    float e3 = (cp1 == rp[mt][1]) ? __expf(0.25f * sacc[mt][s][3]) : 0.f;
                    rsum[mt][0] += e0 + e1;
                    rsum[mt][1] += e2 + e3;
                    ph[mt][2 * s]     = packf16(e0, e1);
                    ph[mt][2 * s + 1] = packf16(e2, e3);
                }
            } else {
                #pragma unroll
                for (int mt = 0; mt < 2; ++mt) {
                    float e0 = __expf(0.25f * sacc[mt][s][0]);
                    float e1 = __expf(0.25f * sacc[mt][s][1]);
                    float e2 = __expf(0.25f * sacc[mt][s][2]);
                    float e3 = __expf(0.25f * sacc[mt][s][3]);
                    rsum[mt][0] += e0 + e1;
                    rsum[mt][1] += e2 + e3;
                    ph[mt][2 * s]     = packf16(e0, e1);
                    ph[mt][2 * s + 1] = packf16(e2, e3);
                }
            }
        }

        uint32_t vh[4];
        ldsm4(vh, sb + SM_VTHI + voff + (uint32_t)(g4 * 16 * 2));
        #pragma unroll
        for (int mt = 0; mt < 2; ++mt)
            #pragma unroll
            for (int sp = 0; sp < 2; ++sp)
                mma16816(oacc[mt][sp], ph[mt], vh[2 * sp], vh[2 * sp + 1]);
    }
}

// ---------------- main kernel ----------------
__global__ void __launch_bounds__(512, 2)
fused_window_attn_mma(const float* __restrict__ x,
                      const float* __restrict__ qkv_b,
                      const float* __restrict__ conv_b,
                      float* __restrict__ out)
{
    extern __shared__ char smemc[];
    const uint32_t sb = smem_u32(smemc);
    float* biasS = (float*)(smemc + SM_BIAS);

    const int t    = threadIdx.x;
    const int wid  = t >> 5;
    const int lane = t & 31;
    const int wm = wid >> 3;
    const int wn = wid & 7;
    const int wi = blockIdx.x;
    const int bz = wi >> 9, by = (wi >> 5) & 15, bx = wi & 31;
    const int z0 = bz * 4, y0 = by * 4, x0 = bx * 4;

    // ---- phase 1: gather x -> A hi (fp16), bias ----
    #pragma unroll
    for (int it = 0; it < 8; ++it) {
        int idx = t + 512 * it;
        int l  = idx & 63;
        int cp = idx >> 6;
        int gz = z0 + (l >> 4);
        int gy = y0 + ((l >> 2) & 3);
        int gx = x0 + (l & 3);
        float v0 = 0.f, v1 = 0.f;
        if (gz < D0 && gy < H0 && gx < W0) {
            size_t base = (size_t)(gz * H0 + gy) * W0 + gx;
            v0 = x[(size_t)(2 * cp) * MTOT + base];
            v1 = x[(size_t)(2 * cp + 1) * MTOT + base];
        }
        *(uint32_t*)(smemc + SM_AHI + (l * AST + 2 * cp) * 2) = packf16(v0, v1);
    }
    if (t < 384) biasS[t] = qkv_b[t];
    __syncthreads();

    const uint32_t aHi = sb + SM_AHI;
    const int fragbase = wn * 8 * 32 + lane;
    const uint4* bhQ = g_bh4 + 0 * 2048 + fragbase;
    const uint4* bhK = g_bh4 + 1 * 2048 + fragbase;
    const uint4* bhV = g_bh4 + 2 * 2048 + fragbase;
    const uint4* bhC = g_bh4 + 3 * 2048 + fragbase;

    const int r8 = lane & 7, g8 = lane >> 3;
    const uint32_t aoff = (uint32_t)(((wm * 32 + r8 + 8 * (g8 & 1)) * AST + 8 * (g8 >> 1)) * 2);

    const int erow = wm * 32 + (lane >> 2);
    const int ecol = wn * 16 + 2 * (lane & 3);

    // ---- fused K+V GEMMs (one A pass, 1-term W-hi) ----
    {
        float accK[2][2][4] = {};
        float accV[2][2][4] = {};
        #pragma unroll
        for (int kk = 0; kk < 8; ++kk) {
            uint4 BK = __ldg(bhK + kk * 32);
            uint4 BV = __ldg(bhV + kk * 32);
            uint32_t ah[2][4];
            #pragma unroll
            for (int mt = 0; mt < 2; ++mt)
                ldsm4(ah[mt], aHi + aoff + (uint32_t)((mt * 16 * AST + kk * 16) * 2));
            #pragma unroll
            for (int mt = 0; mt < 2; ++mt) {
                mma16816(accK[mt][0], ah[mt], BK.x, BK.y);
                mma16816(accK[mt][1], ah[mt], BK.z, BK.w);
                mma16816(accV[mt][0], ah[mt], BV.x, BV.y);
                mma16816(accV[mt][1], ah[mt], BV.z, BV.w);
            }
        }
        // K epilogue -> K hi smem
        #pragma unroll
        for (int mt = 0; mt < 2; ++mt)
            #pragma unroll
            for (int nt = 0; nt < 2; ++nt) {
                int col = ecol + nt * 8;
                float2 bv = *(const float2*)(biasS + 128 + col);
                int r0 = erow + mt * 16;
                *(uint32_t*)(smemc + SM_KHI + (r0 * KST + col) * 2) =
                    packf16(accK[mt][nt][0] + bv.x, accK[mt][nt][1] + bv.y);
                *(uint32_t*)(smemc + SM_KHI + ((r0 + 8) * KST + col) * 2) =
                    packf16(accK[mt][nt][2] + bv.x, accK[mt][nt][3] + bv.y);
            }
        // V epilogue -> Vt hi smem (transposed)
        #pragma unroll
        for (int mt = 0; mt < 2; ++mt)
            #pragma unroll
            for (int nt = 0; nt < 2; ++nt) {
                int col = ecol + nt * 8;
                float2 bv = *(const float2*)(biasS + 256 + col);
                int key = erow + mt * 16;
                int base0 = (col)     * VTST;
                int base1 = (col + 1) * VTST;
                *(__half*)(smemc + SM_VTHI + 2 * (base0 + key))     = __float2half_rn(accV[mt][nt][0] + bv.x);
                *(__half*)(smemc + SM_VTHI + 2 * (base1 + key))     = __float2half_rn(accV[mt][nt][1] + bv.y);
                *(__half*)(smemc + SM_VTHI + 2 * (base0 + key + 8)) = __float2half_rn(accV[mt][nt][2] + bv.x);
                *(__half*)(smemc + SM_VTHI + 2 * (base1 + key + 8)) = __float2half_rn(accV[mt][nt][3] + bv.y);
            }
    }

    // ---- Q GEMM (1-term; hi fragments stay in registers) ----
    uint32_t qh[2][4];
    {
        float acc[2][2][4] = {};
        #pragma unroll
        for (int kk = 0; kk < 8; ++kk) {
            uint4 BH = __ldg(bhQ + kk * 32);
            uint32_t ah[2][4];
            #pragma unroll
            for (int mt = 0; mt < 2; ++mt)
                ldsm4(ah[mt], aHi + aoff + (uint32_t)((mt * 16 * AST + kk * 16) * 2));
            #pragma unroll
            for (int mt = 0; mt < 2; ++mt) {
                mma16816(acc[mt][0], ah[mt], BH.x, BH.y);
                mma16816(acc[mt][1], ah[mt], BH.z, BH.w);
            }
        }
        #pragma unroll
        for (int mt = 0; mt < 2; ++mt)
            #pragma unroll
            for (int nt = 0; nt < 2; ++nt) {
                int col = ecol + nt * 8;
                float2 bv = *(const float2*)(biasS + col);
                qh[mt][2 * nt]     = packf16(acc[mt][nt][0] + bv.x, acc[mt][nt][1] + bv.y);
                qh[mt][2 * nt + 1] = packf16(acc[mt][nt][2] + bv.x, acc[mt][nt][3] + bv.y);
            }
    }
    __syncthreads();   // K/Vt visible; all A reads done

    // ---- attention, warp = (rowhalf wm, head wn) ----
    unsigned long long pm = 0ull;
    if (bz == 7)  pm |= 0xFFFFFFFF00000000ull;
    if (by == 15) pm |= 0xFF00FF00FF00FF00ull;
    if (bx == 31) pm |= 0xCCCCCCCCCCCCCCCCull;

    const int head = wn;
    const uint32_t koff = (uint32_t)(((r8 + 8 * ((lane >> 4) & 1)) * KST
                                      + head * 16 + 8 * ((lane >> 3) & 1)) * 2);
    const uint32_t voff = (uint32_t)(((head * 16 + r8 + 8 * ((lane >> 4) & 1)) * VTST
                                      + 8 * ((lane >> 3) & 1)) * 2);

    float oacc[2][2][4] = {};
    float rsum[2][2] = {};

    if (pm == 0ull)
        attn_loop<false>(sb, qh, pm, wm, lane, koff, voff, oacc, rsum);
    else
        attn_loop<true>(sb, qh, pm, wm, lane, koff, voff, oacc, rsum);

    // quad-reduce row sums, normalize, store Y hi into A region (x is dead)
    #pragma unroll
    for (int mt = 0; mt < 2; ++mt)
        #pragma unroll
        for (int h = 0; h < 2; ++h) {
            rsum[mt][h] += __shfl_xor_sync(0xFFFFFFFFu, rsum[mt][h], 1);
            rsum[mt][h] += __shfl_xor_sync(0xFFFFFFFFu, rsum[mt][h], 2);
            rsum[mt][h] = 1.0f / rsum[mt][h];
        }
    #pragma unroll
    for (int mt = 0; mt < 2; ++mt)
        #pragma unroll
        for (int sp = 0; sp < 2; ++sp) {
            int col = head * 16 + sp * 8 + 2 * (lane & 3);
            int r0 = wm * 32 + mt * 16 + (lane >> 2);
            *(uint32_t*)(smemc + SM_AHI + (r0 * AST + col) * 2) =
                packf16(oacc[mt][sp][0] * rsum[mt][0], oacc[mt][sp][1] * rsum[mt][0]);
            *(uint32_t*)(smemc + SM_AHI + ((r0 + 8) * AST + col) * 2) =
                packf16(oacc[mt][sp][2] * rsum[mt][1], oacc[mt][sp][3] * rsum[mt][1]);
        }
    __syncthreads();   // Y tiles ready

    // ---- conv GEMM (1-term: Y hi x W hi) + scattered output ----
    {
        float acc[2][2][4] = {};
        #pragma unroll
        for (int kk = 0; kk < 8; ++kk) {
            uint4 BH = __ldg(bhC + kk * 32);
            uint32_t ah[2][4];
            #pragma unroll
            for (int mt = 0; mt < 2; ++mt)
                ldsm4(ah[mt], aHi + aoff + (uint32_t)((mt * 16 * AST + kk * 16) * 2));
            #pragma unroll
            for (int mt = 0; mt < 2; ++mt) {
                mma16816(acc[mt][0], ah[mt], BH.x, BH.y);
                mma16816(acc[mt][1], ah[mt], BH.z, BH.w);
            }
        }
        #pragma unroll
        for (int mt = 0; mt < 2; ++mt) {
            int m0 = erow + mt * 16;
            int m1 = m0 + 8;
            int gz0 = z0 + (m0 >> 4), gy0 = y0 + ((m0 >> 2) & 3), gx0 = x0 + (m0 & 3);
            int gz1 = z0 + (m1 >> 4), gy1 = y0 + ((m1 >> 2) & 3), gx1 = x0 + (m1 & 3);
            bool ok0 = (gz0 < D0 && gy0 < H0 && gx0 < W0);
            bool ok1 = (gz1 < D0 && gy1 < H0 && gx1 < W0);
            size_t va0 = (size_t)(gz0 * H0 + gy0) * W0 + gx0;
            size_t va1 = (size_t)(gz1 * H0 + gy1) * W0 + gx1;
            #pragma unroll
            for (int nt = 0; nt < 2; ++nt) {
                int o = ecol + nt * 8;
                float2 cb = *(const float2*)(conv_b + o);
                if (ok0) {
                    out[(size_t)o * MTOT + va0]       = acc[mt][nt][0] + cb.x;
                    out[(size_t)(o + 1) * MTOT + va0] = acc[mt][nt][1] + cb.y;
                }
                if (ok1) {
                    out[(size_t)o * MTOT + va1]       = acc[mt][nt][2] + cb.x;
                    out[(size_t)(o + 1) * MTOT + va1] = acc[mt][nt][3] + cb.y;
                }
            }
        }
    }
}

extern "C" void kernel_launch(void* const* d_in, const int* in_sizes, int n_in,
                              void* d_out, int out_size)
{
    const float* x      = (const float*)d_in[0];
    const float* qkv_b  = (const float*)d_in[2];
    const float* conv_b = (const float*)d_in[4];
    float* out = (float*)d_out;

    prep_weights<<<32, 256>>>((const float*)d_in[1], (const float*)d_in[3]);

    cudaFuncSetAttribute(fused_window_attn_mma,
                         cudaFuncAttributeMaxDynamicSharedMemorySize, SMEM_BYTES);

    fused_window_attn_mma<<<4096, 512, SMEM_BYTES>>>(x, qkv_b, conv_b, out);
}